// round 8
// baseline (speedup 1.0000x reference)
#include <cuda_runtime.h>
#include <cuda_fp16.h>
#include <cstdint>

#define NB 4096
#define NT 168
#define NH 128
#define NG 512
#define NO 24

// ------------------------- device scratch -------------------------
__device__ __half g_ench[NB * NT * NH];  // encoder hidden states (B*T, H) fp16
__device__ __half g_Ueh [NB * NT * NH];  // Ua @ enc_outs        (B*T, H) fp16
__device__ float g_h  [NB * NH];
__device__ float g_c  [NB * NH];
__device__ float g_ctx[NB * NH];
__device__ float g_pred[NB];
__device__ __half g_WencP[8 * 8 * 8 * 32 * 4];  // enc Whh B-frags [wid][kt][j][lane][4]
__device__ __half g_UaP  [16 * 8 * 32 * 4];     // Ua B-frags [nt][kt][lane][4]
__device__ __half g_WdP  [8 * 16 * 8 * 32 * 4]; // dec [Wih(ctx)|Whh] B-frags, K=256
__device__ float g_encBp[NG];           // enc bias, n = u*4+gate
__device__ float g_wihp [NG];           // enc Wih,  n = u*4+gate
__device__ float g_decBp[NG];           // dec bias, n = u*4+gate
__device__ float g_dinW [NG];           // dec Wih col 0 (din), n = u*4+gate
__device__ float g_WaT [NH * NH];       // Wa transposed: [k][u]

// fast activations: tanh.approx (1 MUFU); sigmoid via tanh identity (1 MUFU + 2 FMA)
__device__ __forceinline__ float ftanh_fast(float x) { asm("tanh.approx.f32 %0, %0;" : "+f"(x)); return x; }
__device__ __forceinline__ float fsig_fast(float x)  { return 0.5f + 0.5f * ftanh_fast(0.5f * x); }
// paired tanh: 2 values per MUFU op
__device__ __forceinline__ __half2 htanh2(__half2 x) {
    uint32_t v = *(uint32_t*)&x;
    asm("tanh.approx.f16x2 %0, %0;" : "+r"(v));
    return *(__half2*)&v;
}

// ------------------------- mma helpers -------------------------
__device__ __forceinline__ void ldmA(uint32_t a[4], const __half* p) {
    uint32_t addr = (uint32_t)__cvta_generic_to_shared(p);
    asm volatile("ldmatrix.sync.aligned.m8n8.x4.shared.b16 {%0,%1,%2,%3}, [%4];"
        : "=r"(a[0]), "=r"(a[1]), "=r"(a[2]), "=r"(a[3]) : "r"(addr));
}
__device__ __forceinline__ void mma16816(float c[4], const uint32_t a[4], uint2 b) {
    asm volatile("mma.sync.aligned.m16n8k16.row.col.f32.f16.f16.f32 "
        "{%0,%1,%2,%3},{%4,%5,%6,%7},{%8,%9},{%0,%1,%2,%3};"
        : "+f"(c[0]), "+f"(c[1]), "+f"(c[2]), "+f"(c[3])
        : "r"(a[0]), "r"(a[1]), "r"(a[2]), "r"(a[3]), "r"(b.x), "r"(b.y));
}

// ------------------------- weight packing -------------------------
__global__ void pack_kernel(const float* __restrict__ encWih,
                            const float* __restrict__ encWhh,
                            const float* __restrict__ encBih, const float* __restrict__ encBhh,
                            const float* __restrict__ Wa, const float* __restrict__ Ua,
                            const float* __restrict__ decWih, const float* __restrict__ decWhh,
                            const float* __restrict__ decBih, const float* __restrict__ decBhh)
{
    int stride = gridDim.x * blockDim.x;
    int i0 = blockIdx.x * blockDim.x + threadIdx.x;

    for (int idx = i0; idx < 8 * 8 * 8 * 32 * 4; idx += stride) {
        int q = idx & 3, lane = (idx >> 2) & 31;
        int rest = idx >> 7;
        int j = rest & 7, kt = (rest >> 3) & 7, wid = rest >> 6;
        int g = lane >> 2, tg = lane & 3;
        int n = wid * 64 + j * 8 + g;
        int u = n >> 2, gate = n & 3;
        int k = kt * 16 + ((q < 2) ? (tg * 2 + q) : (tg * 2 + 8 + (q - 2)));
        g_WencP[idx] = __float2half_rn(encWhh[(gate * 128 + u) * NH + k]);
    }
    for (int idx = i0; idx < 8 * 16 * 8 * 32 * 4; idx += stride) {
        int q = idx & 3, lane = (idx >> 2) & 31;
        int rest = idx >> 7;
        int j = rest & 7, kt = (rest >> 3) & 15, wid = rest >> 7;
        int g = lane >> 2, tg = lane & 3;
        int n = wid * 64 + j * 8 + g;
        int u = n >> 2, gate = n & 3;
        int k = kt * 16 + ((q < 2) ? (tg * 2 + q) : (tg * 2 + 8 + (q - 2)));
        float v = (k < NH) ? decWih[(gate * 128 + u) * (NH + 1) + 1 + k]
                           : decWhh[(gate * 128 + u) * NH + (k - NH)];
        g_WdP[idx] = __float2half_rn(v);
    }
    for (int idx = i0; idx < 16 * 8 * 32 * 4; idx += stride) {
        int q = idx & 3, lane = (idx >> 2) & 31;
        int rest = idx >> 7;
        int kt = rest & 7, nt = rest >> 3;
        int g = lane >> 2, tg = lane & 3;
        int n = nt * 8 + g;
        int k = kt * 16 + ((q < 2) ? (tg * 2 + q) : (tg * 2 + 8 + (q - 2)));
        g_UaP[idx] = __float2half_rn(Ua[n * NH + k]);
    }
    for (int i = i0; i < NH * NH; i += stride) {
        int k = i / NH, u = i % NH;
        g_WaT[i] = Wa[u * NH + k];
    }
    for (int i = i0; i < NG; i += stride) {
        int u = i >> 2, gate = i & 3;
        g_encBp[i] = encBih[gate * 128 + u] + encBhh[gate * 128 + u];
        g_wihp[i]  = encWih[gate * 128 + u];
        g_decBp[i] = decBih[gate * 128 + u] + decBhh[gate * 128 + u];
        g_dinW[i]  = decWih[(gate * 128 + u) * (NH + 1)];
    }
}

// ------------------------- encoder (HMMA, one launch, 168 steps) -------------------------
__global__ void __launch_bounds__(256) enc_kernel(const float* __restrict__ x)
{
    __shared__ __half hsh[32][136];
    __shared__ float biassh[NG], wihsh[NG];
    int tid = threadIdx.x;
    int wid = tid >> 5, lane = tid & 31;
    int b0 = blockIdx.x * 32;
    int g = lane >> 2, tg = lane & 3, tg2 = tg >> 1;
    int odd = tg & 1;
    int lrow = lane & 15;
    int lcol = (lane >> 4) << 3;

    for (int i = tid; i < NG; i += 256) { biassh[i] = g_encBp[i]; wihsh[i] = g_wihp[i]; }
    for (int i = tid; i < 32 * 136; i += 256) ((__half*)hsh)[i] = __ushort_as_half(0);

    float cst[16];
    #pragma unroll
    for (int i = 0; i < 16; i++) cst[i] = 0.f;

    const uint2* wbase = ((const uint2*)g_WencP) + wid * 2048 + lane;
    __syncthreads();

    for (int t = 0; t < NT; t++) {
        float xv[2];
        #pragma unroll
        for (int mi = 0; mi < 2; mi++)
            xv[mi] = x[(b0 + mi * 16 + g + (odd ? 8 : 0)) * NT + t];

        float acc[2][8][4];
        #pragma unroll
        for (int mi = 0; mi < 2; mi++)
            #pragma unroll
            for (int j = 0; j < 8; j++)
                #pragma unroll
                for (int q = 0; q < 4; q++) acc[mi][j][q] = 0.f;

        #pragma unroll
        for (int kt = 0; kt < 8; kt++) {
            uint32_t a[2][4];
            #pragma unroll
            for (int mi = 0; mi < 2; mi++)
                ldmA(a[mi], &hsh[mi * 16 + lrow][kt * 16 + lcol]);
            #pragma unroll
            for (int j = 0; j < 8; j++) {
                uint2 b = wbase[(kt * 8 + j) * 32];
                mma16816(acc[0][j], a[0], b);
                mma16816(acc[1][j], a[1], b);
            }
        }
        __syncthreads();

        #pragma unroll
        for (int mi = 0; mi < 2; mi++) {
            int row = mi * 16 + g + (odd ? 8 : 0);
            #pragma unroll
            for (int j = 0; j < 8; j++) {
                float t0 = __shfl_xor_sync(0xffffffffu, acc[mi][j][0], 1);
                float t1 = __shfl_xor_sync(0xffffffffu, acc[mi][j][1], 1);
                float t2 = __shfl_xor_sync(0xffffffffu, acc[mi][j][2], 1);
                float t3 = __shfl_xor_sync(0xffffffffu, acc[mi][j][3], 1);
                float gi, gf, gg, go;
                if (!odd) { gi = acc[mi][j][0]; gf = acc[mi][j][1]; gg = t0; go = t1; }
                else      { gi = t2; gf = t3; gg = acc[mi][j][2]; go = acc[mi][j][3]; }
                int u = wid * 16 + j * 2 + tg2;
                float4 bi = *(const float4*)&biassh[u * 4];
                float4 wi = *(const float4*)&wihsh[u * 4];
                gi += bi.x + xv[mi] * wi.x;
                gf += bi.y + xv[mi] * wi.y;
                gg += bi.z + xv[mi] * wi.z;
                go += bi.w + xv[mi] * wi.w;
                float c = fsig_fast(gf) * cst[mi * 8 + j] + fsig_fast(gi) * ftanh_fast(gg);
                cst[mi * 8 + j] = c;
                float h = fsig_fast(go) * ftanh_fast(c);
                hsh[row][u] = __float2half_rn(h);
            }
        }
        __syncthreads();

        for (int i = tid; i < 512; i += 256) {
            int r = i >> 4, ch = i & 15;
            uint4 v = *(uint4*)&hsh[r][ch * 8];
            *(uint4*)&g_ench[(size_t)(b0 + r) * (NT * NH) + (size_t)t * NH + ch * 8] = v;
        }
    }
    __syncthreads();
    for (int i = tid; i < 32 * NH; i += 256) {
        int r = i >> 7, u2 = i & 127;
        g_h[(b0 + r) * NH + u2] = __half2float(hsh[r][u2]);
    }
    #pragma unroll
    for (int mi = 0; mi < 2; mi++) {
        int row = mi * 16 + g + (odd ? 8 : 0);
        #pragma unroll
        for (int j = 0; j < 8; j++) {
            int u = wid * 16 + j * 2 + tg2;
            g_c[(b0 + row) * NH + u] = cst[mi * 8 + j];
        }
    }
}

// ------------------------- Ue = enc_outs @ Ua^T (HMMA) -------------------------
__global__ void __launch_bounds__(256) ue_kernel()
{
    __shared__ __half ash[32][136];
    int tid = threadIdx.x;
    int wid = tid >> 5, lane = tid & 31;
    size_t row0 = (size_t)blockIdx.x * 32;

    for (int i = tid; i < 512; i += 256) {
        int r = i >> 4, ch = i & 15;
        *(uint4*)&ash[r][ch * 8] = *(const uint4*)&g_ench[(row0 + r) * NH + ch * 8];
    }
    __syncthreads();

    int mi = wid & 1, nw = wid >> 1;
    int lrow = lane & 15, lcol = (lane >> 4) << 3;
    float acc[4][4];
    #pragma unroll
    for (int nt = 0; nt < 4; nt++)
        #pragma unroll
        for (int q = 0; q < 4; q++) acc[nt][q] = 0.f;

    const uint2* ub = (const uint2*)g_UaP;
    #pragma unroll
    for (int kt = 0; kt < 8; kt++) {
        uint32_t a[4];
        ldmA(a, &ash[mi * 16 + lrow][kt * 16 + lcol]);
        #pragma unroll
        for (int nt = 0; nt < 4; nt++) {
            int ntg = nw * 4 + nt;
            uint2 b = ub[(ntg * 8 + kt) * 32 + lane];
            mma16816(acc[nt], a, b);
        }
    }
    __syncthreads();

    int g = lane >> 2, tg = lane & 3;
    #pragma unroll
    for (int nt = 0; nt < 4; nt++) {
        int n = (nw * 4 + nt) * 8 + tg * 2;
        *(__half2*)&ash[mi * 16 + g][n]     = __floats2half2_rn(acc[nt][0], acc[nt][1]);
        *(__half2*)&ash[mi * 16 + 8 + g][n] = __floats2half2_rn(acc[nt][2], acc[nt][3]);
    }
    __syncthreads();
    for (int i = tid; i < 512; i += 256) {
        int r = i >> 4, ch = i & 15;
        *(uint4*)&g_Ueh[(row0 + r) * NH + ch * 8] = *(uint4*)&ash[r][ch * 8];
    }
}

// ------------------------- decoder attention (fused single pass, f16x2 tanh) ---------------
// block: 256 thr = 8 warps; warp = one batch row. Lanes 0-15 even t, 16-31 odd t.
// No max subtraction: |score| <= ||va||_1 ~ 9.2, exp() safe in fp32.
__global__ void __launch_bounds__(256) att_kernel(const float* __restrict__ va)
{
    __shared__ float hsh[8][NH];
    __shared__ float qsh[8][NH];
    int tid = threadIdx.x;
    int b0 = blockIdx.x * 8;
    for (int i = tid; i < 8 * NH; i += 256) hsh[i >> 7][i & 127] = g_h[b0 * NH + i];
    __syncthreads();

    // q = h @ Wa^T : thread (u, rh) covers 4 rows
    {
        int u = tid & 127, rh = tid >> 7;
        float qa[4] = {0.f, 0.f, 0.f, 0.f};
        #pragma unroll 4
        for (int k = 0; k < NH; k++) {
            float w = g_WaT[k * NH + u];
            #pragma unroll
            for (int r = 0; r < 4; r++) qa[r] += w * hsh[rh * 4 + r][k];
        }
        #pragma unroll
        for (int r = 0; r < 4; r++) qsh[rh * 4 + r][u] = qa[r];
    }
    __syncthreads();

    int wid = tid >> 5, lane = tid & 31;
    int sub = lane & 15;
    int b = b0 + wid;

    // q as half2 (pre-activation |Ue+q| ~ O(1): half quantization ~1e-4, below tanh.approx err)
    float4 qaf = *(float4*)&qsh[wid][sub * 8];
    float4 qbf = *(float4*)&qsh[wid][sub * 8 + 4];
    __half2 qh[4] = { __floats2half2_rn(qaf.x, qaf.y), __floats2half2_rn(qaf.z, qaf.w),
                      __floats2half2_rn(qbf.x, qbf.y), __floats2half2_rn(qbf.z, qbf.w) };
    float4 va0 = *(const float4*)&va[sub * 8];
    float4 va1 = *(const float4*)&va[sub * 8 + 4];

    const uint4* uep = (const uint4*)(g_Ueh + (size_t)b * NT * NH) + lane;
    const uint4* ep  = (const uint4*)(g_ench + (size_t)b * NT * NH) + lane;

    float ca[8];
    #pragma unroll
    for (int j = 0; j < 8; j++) ca[j] = 0.f;
    float Z = 0.f;

    #pragma unroll 2
    for (int i = 0; i < NT / 2; i++) {
        uint4 ue = uep[i * 32];
        uint4 en = ep[i * 32];
        // energy + tanh in f16x2: 4 HADD2 + 4 MUFU (vs 8 MUFU)
        __half2 t0 = htanh2(__hadd2(*(__half2*)&ue.x, qh[0]));
        __half2 t1 = htanh2(__hadd2(*(__half2*)&ue.y, qh[1]));
        __half2 t2 = htanh2(__hadd2(*(__half2*)&ue.z, qh[2]));
        __half2 t3 = htanh2(__hadd2(*(__half2*)&ue.w, qh[3]));
        float2 f0 = __half22float2(t0);
        float2 f1 = __half22float2(t1);
        float2 f2 = __half22float2(t2);
        float2 f3 = __half22float2(t3);
        float s = f0.x * va0.x + f0.y * va0.y + f1.x * va0.z + f1.y * va0.w
                + f2.x * va1.x + f2.y * va1.y + f3.x * va1.z + f3.y * va1.w;
        s += __shfl_xor_sync(0xffffffffu, s, 8);
        s += __shfl_xor_sync(0xffffffffu, s, 4);
        s += __shfl_xor_sync(0xffffffffu, s, 2);
        s += __shfl_xor_sync(0xffffffffu, s, 1);
        float w = __expf(s);
        Z += w;
        float2 n0 = __half22float2(*(__half2*)&en.x);
        float2 n1 = __half22float2(*(__half2*)&en.y);
        float2 n2 = __half22float2(*(__half2*)&en.z);
        float2 n3 = __half22float2(*(__half2*)&en.w);
        ca[0] += w * n0.x; ca[1] += w * n0.y;
        ca[2] += w * n1.x; ca[3] += w * n1.y;
        ca[4] += w * n2.x; ca[5] += w * n2.y;
        ca[6] += w * n3.x; ca[7] += w * n3.y;
    }
    // merge even/odd-t halves (lane j pairs with j+16, same h slice)
    Z += __shfl_xor_sync(0xffffffffu, Z, 16);
    #pragma unroll
    for (int j = 0; j < 8; j++) ca[j] += __shfl_xor_sync(0xffffffffu, ca[j], 16);
    float invZ = __fdividef(1.f, Z);
    if (lane < 16) {
        float4 o0 = {ca[0] * invZ, ca[1] * invZ, ca[2] * invZ, ca[3] * invZ};
        float4 o1 = {ca[4] * invZ, ca[5] * invZ, ca[6] * invZ, ca[7] * invZ};
        *(float4*)&g_ctx[b * NH + sub * 8]     = o0;
        *(float4*)&g_ctx[b * NH + sub * 8 + 4] = o1;
    }
}

// ------------------------- decoder LSTM cell + fc (HMMA, per step) -------------------------
// block: 256 thr = 8 warps, 16 rows (grid 256 > 148 SMs). K=256 over fp16 [ctx|h].
__global__ void __launch_bounds__(256) cell_kernel(const float* __restrict__ x,
                                                   const float* __restrict__ fcW,
                                                   const float* __restrict__ fcb,
                                                   float* __restrict__ out, int step)
{
    __shared__ __half ash[16][264];
    __shared__ float biassh[NG], dinwsh[NG];
    __shared__ float dinsh[16];
    __shared__ float hout[16][NH];
    int tid = threadIdx.x;
    int wid = tid >> 5, lane = tid & 31;
    int b0 = blockIdx.x * 16;
    int g = lane >> 2, tg = lane & 3, tg2 = tg >> 1;
    int odd = tg & 1;
    int lrow = lane & 15;
    int lcol = (lane >> 4) << 3;

    for (int i = tid; i < NG; i += 256) { biassh[i] = g_decBp[i]; dinwsh[i] = g_dinW[i]; }
    for (int i = tid; i < 16 * 64; i += 256) {
        int r = i >> 6, k2 = i & 63;
        float2 cv = ((const float2*)g_ctx)[(size_t)(b0 + r) * 64 + k2];
        float2 hv = ((const float2*)g_h)  [(size_t)(b0 + r) * 64 + k2];
        *(__half2*)&ash[r][k2 * 2]       = __floats2half2_rn(cv.x, cv.y);
        *(__half2*)&ash[r][128 + k2 * 2] = __floats2half2_rn(hv.x, hv.y);
    }
    if (tid < 16) dinsh[tid] = (step == 0) ? x[(b0 + tid) * NT + (NT - 1)] : g_pred[b0 + tid];
    __syncthreads();

    float acc[8][4];
    #pragma unroll
    for (int j = 0; j < 8; j++)
        #pragma unroll
        for (int q = 0; q < 4; q++) acc[j][q] = 0.f;

    const uint2* wbase = ((const uint2*)g_WdP) + wid * 4096 + lane;
    #pragma unroll
    for (int kt = 0; kt < 16; kt++) {
        uint32_t a[4];
        ldmA(a, &ash[lrow][kt * 16 + lcol]);
        #pragma unroll
        for (int j = 0; j < 8; j++) {
            uint2 b = wbase[(kt * 8 + j) * 32];
            mma16816(acc[j], a, b);
        }
    }

    {
        int row = g + (odd ? 8 : 0);
        float dv = dinsh[row];
        #pragma unroll
        for (int j = 0; j < 8; j++) {
            float t0 = __shfl_xor_sync(0xffffffffu, acc[j][0], 1);
            float t1 = __shfl_xor_sync(0xffffffffu, acc[j][1], 1);
            float t2 = __shfl_xor_sync(0xffffffffu, acc[j][2], 1);
            float t3 = __shfl_xor_sync(0xffffffffu, acc[j][3], 1);
            float gi, gf, gg, go;
            if (!odd) { gi = acc[j][0]; gf = acc[j][1]; gg = t0; go = t1; }
            else      { gi = t2; gf = t3; gg = acc[j][2]; go = acc[j][3]; }
            int u = wid * 16 + j * 2 + tg2;
            float4 bi = *(const float4*)&biassh[u * 4];
            float4 wi = *(const float4*)&dinwsh[u * 4];
            gi += bi.x + dv * wi.x;
            gf += bi.y + dv * wi.y;
            gg += bi.z + dv * wi.z;
            go += bi.w + dv * wi.w;
            int b = b0 + row;
            float cold = g_c[b * NH + u];
            float cn = fsig_fast(gf) * cold + fsig_fast(gi) * ftanh_fast(gg);
            float hn = fsig_fast(go) * ftanh_fast(cn);
            g_c[b * NH + u] = cn;
            g_h[b * NH + u] = hn;
            hout[row][u] = hn;
        }
    }
    __syncthreads();

    // pred = h2 @ fcW^T + fcb ; warp handles 2 rows
    float fw0 = fcW[lane], fw1 = fcW[lane + 32], fw2 = fcW[lane + 64], fw3 = fcW[lane + 96];
    #pragma unroll
    for (int rr = 0; rr < 2; rr++) {
        int r = wid * 2 + rr;
        float s = hout[r][lane] * fw0 + hout[r][lane + 32] * fw1
                + hout[r][lane + 64] * fw2 + hout[r][lane + 96] * fw3;
        #pragma unroll
        for (int off = 16; off > 0; off >>= 1) s += __shfl_xor_sync(0xffffffffu, s, off);
        if (lane == 0) {
            float p = s + fcb[0];
            out[(b0 + r) * NO + step] = p;
            g_pred[b0 + r] = p;
        }
    }
}

// ------------------------- launch -------------------------
extern "C" void kernel_launch(void* const* d_in, const int* in_sizes, int n_in,
                              void* d_out, int out_size)
{
    const float* x      = (const float*)d_in[0];
    const float* encWih = (const float*)d_in[1];
    const float* encWhh = (const float*)d_in[2];
    const float* encBih = (const float*)d_in[3];
    const float* encBhh = (const float*)d_in[4];
    const float* Wa     = (const float*)d_in[5];
    const float* Ua     = (const float*)d_in[6];
    const float* va     = (const float*)d_in[7];
    const float* decWih = (const float*)d_in[8];
    const float* decWhh = (const float*)d_in[9];
    const float* decBih = (const float*)d_in[10];
    const float* decBhh = (const float*)d_in[11];
    const float* fcW    = (const float*)d_in[12];
    const float* fcb    = (const float*)d_in[13];
    float* out = (float*)d_out;

    pack_kernel<<<256, 256>>>(encWih, encWhh, encBih, encBhh, Wa, Ua,
                              decWih, decWhh, decBih, decBhh);
    enc_kernel<<<NB / 32, 256>>>(x);
    ue_kernel<<<NB * NT / 32, 256>>>();
    for (int d = 0; d < NO; d++) {
        att_kernel<<<NB / 8, 256>>>(va);
        cell_kernel<<<NB / 16, 256>>>(x, fcW, fcb, out, d);
    }
}

// round 9
// speedup vs baseline: 1.1163x; 1.1163x over previous
#include <cuda_runtime.h>
#include <cuda_fp16.h>
#include <cstdint>

#define NB 4096
#define NT 168
#define NH 128
#define NG 512
#define NO 24

// ------------------------- device scratch -------------------------
__device__ __half g_ench[NB * NT * NH];  // encoder hidden states (B*T, H) fp16
__device__ __half g_Ueh [NB * NT * NH];  // Ua @ enc_outs        (B*T, H) fp16
__device__ float g_h  [NB * NH];
__device__ float g_c  [NB * NH];
__device__ float g_ctx[NB * NH];
__device__ float g_pred[NB];
__device__ __half g_WencP[8 * 8 * 8 * 32 * 4];  // enc Whh B-frags [wid][kt][j][lane][4]
__device__ __half g_UaP  [16 * 8 * 32 * 4];     // Ua B-frags [nt][kt][lane][4]
__device__ __half g_WdP  [8 * 16 * 8 * 32 * 4]; // dec [Wih(ctx)|Whh] B-frags, K=256
__device__ float g_encBp[NG];           // enc bias, n = u*4+gate
__device__ float g_wihp [NG];           // enc Wih,  n = u*4+gate
__device__ float g_decBp[NG];           // dec bias, n = u*4+gate
__device__ float g_dinW [NG];           // dec Wih col 0 (din), n = u*4+gate
__device__ float g_WaT [NH * NH];       // Wa transposed: [k][u]

// fast activations: tanh.approx (1 MUFU); sigmoid via tanh identity (1 MUFU + 2 FMA)
__device__ __forceinline__ float ftanh_fast(float x) { asm("tanh.approx.f32 %0, %0;" : "+f"(x)); return x; }
__device__ __forceinline__ float fsig_fast(float x)  { return 0.5f + 0.5f * ftanh_fast(0.5f * x); }

// ------------------------- mma helpers -------------------------
__device__ __forceinline__ void ldmA(uint32_t a[4], const __half* p) {
    uint32_t addr = (uint32_t)__cvta_generic_to_shared(p);
    asm volatile("ldmatrix.sync.aligned.m8n8.x4.shared.b16 {%0,%1,%2,%3}, [%4];"
        : "=r"(a[0]), "=r"(a[1]), "=r"(a[2]), "=r"(a[3]) : "r"(addr));
}
__device__ __forceinline__ void mma16816(float c[4], const uint32_t a[4], uint2 b) {
    asm volatile("mma.sync.aligned.m16n8k16.row.col.f32.f16.f16.f32 "
        "{%0,%1,%2,%3},{%4,%5,%6,%7},{%8,%9},{%0,%1,%2,%3};"
        : "+f"(c[0]), "+f"(c[1]), "+f"(c[2]), "+f"(c[3])
        : "r"(a[0]), "r"(a[1]), "r"(a[2]), "r"(a[3]), "r"(b.x), "r"(b.y));
}

// ------------------------- weight packing -------------------------
__global__ void pack_kernel(const float* __restrict__ encWih,
                            const float* __restrict__ encWhh,
                            const float* __restrict__ encBih, const float* __restrict__ encBhh,
                            const float* __restrict__ Wa, const float* __restrict__ Ua,
                            const float* __restrict__ decWih, const float* __restrict__ decWhh,
                            const float* __restrict__ decBih, const float* __restrict__ decBhh)
{
    int stride = gridDim.x * blockDim.x;
    int i0 = blockIdx.x * blockDim.x + threadIdx.x;

    for (int idx = i0; idx < 8 * 8 * 8 * 32 * 4; idx += stride) {
        int q = idx & 3, lane = (idx >> 2) & 31;
        int rest = idx >> 7;
        int j = rest & 7, kt = (rest >> 3) & 7, wid = rest >> 6;
        int g = lane >> 2, tg = lane & 3;
        int n = wid * 64 + j * 8 + g;
        int u = n >> 2, gate = n & 3;
        int k = kt * 16 + ((q < 2) ? (tg * 2 + q) : (tg * 2 + 8 + (q - 2)));
        g_WencP[idx] = __float2half_rn(encWhh[(gate * 128 + u) * NH + k]);
    }
    for (int idx = i0; idx < 8 * 16 * 8 * 32 * 4; idx += stride) {
        int q = idx & 3, lane = (idx >> 2) & 31;
        int rest = idx >> 7;
        int j = rest & 7, kt = (rest >> 3) & 15, wid = rest >> 7;
        int g = lane >> 2, tg = lane & 3;
        int n = wid * 64 + j * 8 + g;
        int u = n >> 2, gate = n & 3;
        int k = kt * 16 + ((q < 2) ? (tg * 2 + q) : (tg * 2 + 8 + (q - 2)));
        float v = (k < NH) ? decWih[(gate * 128 + u) * (NH + 1) + 1 + k]
                           : decWhh[(gate * 128 + u) * NH + (k - NH)];
        g_WdP[idx] = __float2half_rn(v);
    }
    for (int idx = i0; idx < 16 * 8 * 32 * 4; idx += stride) {
        int q = idx & 3, lane = (idx >> 2) & 31;
        int rest = idx >> 7;
        int kt = rest & 7, nt = rest >> 3;
        int g = lane >> 2, tg = lane & 3;
        int n = nt * 8 + g;
        int k = kt * 16 + ((q < 2) ? (tg * 2 + q) : (tg * 2 + 8 + (q - 2)));
        g_UaP[idx] = __float2half_rn(Ua[n * NH + k]);
    }
    for (int i = i0; i < NH * NH; i += stride) {
        int k = i / NH, u = i % NH;
        g_WaT[i] = Wa[u * NH + k];
    }
    for (int i = i0; i < NG; i += stride) {
        int u = i >> 2, gate = i & 3;
        g_encBp[i] = encBih[gate * 128 + u] + encBhh[gate * 128 + u];
        g_wihp[i]  = encWih[gate * 128 + u];
        g_decBp[i] = decBih[gate * 128 + u] + decBhh[gate * 128 + u];
        g_dinW[i]  = decWih[(gate * 128 + u) * (NH + 1)];
    }
}

// ------------------------- encoder (HMMA, one launch, 168 steps) -------------------------
__global__ void __launch_bounds__(256) enc_kernel(const float* __restrict__ x)
{
    __shared__ __half hsh[32][136];
    __shared__ float biassh[NG], wihsh[NG];
    int tid = threadIdx.x;
    int wid = tid >> 5, lane = tid & 31;
    int b0 = blockIdx.x * 32;
    int g = lane >> 2, tg = lane & 3, tg2 = tg >> 1;
    int odd = tg & 1;
    int lrow = lane & 15;
    int lcol = (lane >> 4) << 3;

    for (int i = tid; i < NG; i += 256) { biassh[i] = g_encBp[i]; wihsh[i] = g_wihp[i]; }
    for (int i = tid; i < 32 * 136; i += 256) ((__half*)hsh)[i] = __ushort_as_half(0);

    float cst[16];
    #pragma unroll
    for (int i = 0; i < 16; i++) cst[i] = 0.f;

    const uint2* wbase = ((const uint2*)g_WencP) + wid * 2048 + lane;
    __syncthreads();

    for (int t = 0; t < NT; t++) {
        float xv[2];
        #pragma unroll
        for (int mi = 0; mi < 2; mi++)
            xv[mi] = x[(b0 + mi * 16 + g + (odd ? 8 : 0)) * NT + t];

        float acc[2][8][4];
        #pragma unroll
        for (int mi = 0; mi < 2; mi++)
            #pragma unroll
            for (int j = 0; j < 8; j++)
                #pragma unroll
                for (int q = 0; q < 4; q++) acc[mi][j][q] = 0.f;

        #pragma unroll
        for (int kt = 0; kt < 8; kt++) {
            uint32_t a[2][4];
            #pragma unroll
            for (int mi = 0; mi < 2; mi++)
                ldmA(a[mi], &hsh[mi * 16 + lrow][kt * 16 + lcol]);
            #pragma unroll
            for (int j = 0; j < 8; j++) {
                uint2 b = wbase[(kt * 8 + j) * 32];
                mma16816(acc[0][j], a[0], b);
                mma16816(acc[1][j], a[1], b);
            }
        }
        __syncthreads();

        #pragma unroll
        for (int mi = 0; mi < 2; mi++) {
            int row = mi * 16 + g + (odd ? 8 : 0);
            #pragma unroll
            for (int j = 0; j < 8; j++) {
                float t0 = __shfl_xor_sync(0xffffffffu, acc[mi][j][0], 1);
                float t1 = __shfl_xor_sync(0xffffffffu, acc[mi][j][1], 1);
                float t2 = __shfl_xor_sync(0xffffffffu, acc[mi][j][2], 1);
                float t3 = __shfl_xor_sync(0xffffffffu, acc[mi][j][3], 1);
                float gi, gf, gg, go;
                if (!odd) { gi = acc[mi][j][0]; gf = acc[mi][j][1]; gg = t0; go = t1; }
                else      { gi = t2; gf = t3; gg = acc[mi][j][2]; go = acc[mi][j][3]; }
                int u = wid * 16 + j * 2 + tg2;
                float4 bi = *(const float4*)&biassh[u * 4];
                float4 wi = *(const float4*)&wihsh[u * 4];
                gi += bi.x + xv[mi] * wi.x;
                gf += bi.y + xv[mi] * wi.y;
                gg += bi.z + xv[mi] * wi.z;
                go += bi.w + xv[mi] * wi.w;
                float c = fsig_fast(gf) * cst[mi * 8 + j] + fsig_fast(gi) * ftanh_fast(gg);
                cst[mi * 8 + j] = c;
                float h = fsig_fast(go) * ftanh_fast(c);
                hsh[row][u] = __float2half_rn(h);
            }
        }
        __syncthreads();

        for (int i = tid; i < 512; i += 256) {
            int r = i >> 4, ch = i & 15;
            uint4 v = *(uint4*)&hsh[r][ch * 8];
            *(uint4*)&g_ench[(size_t)(b0 + r) * (NT * NH) + (size_t)t * NH + ch * 8] = v;
        }
    }
    __syncthreads();
    for (int i = tid; i < 32 * NH; i += 256) {
        int r = i >> 7, u2 = i & 127;
        g_h[(b0 + r) * NH + u2] = __half2float(hsh[r][u2]);
    }
    #pragma unroll
    for (int mi = 0; mi < 2; mi++) {
        int row = mi * 16 + g + (odd ? 8 : 0);
        #pragma unroll
        for (int j = 0; j < 8; j++) {
            int u = wid * 16 + j * 2 + tg2;
            g_c[(b0 + row) * NH + u] = cst[mi * 8 + j];
        }
    }
}

// ------------------------- Ue = enc_outs @ Ua^T (HMMA) -------------------------
__global__ void __launch_bounds__(256) ue_kernel()
{
    __shared__ __half ash[32][136];
    int tid = threadIdx.x;
    int wid = tid >> 5, lane = tid & 31;
    size_t row0 = (size_t)blockIdx.x * 32;

    for (int i = tid; i < 512; i += 256) {
        int r = i >> 4, ch = i & 15;
        *(uint4*)&ash[r][ch * 8] = *(const uint4*)&g_ench[(row0 + r) * NH + ch * 8];
    }
    __syncthreads();

    int mi = wid & 1, nw = wid >> 1;
    int lrow = lane & 15, lcol = (lane >> 4) << 3;
    float acc[4][4];
    #pragma unroll
    for (int nt = 0; nt < 4; nt++)
        #pragma unroll
        for (int q = 0; q < 4; q++) acc[nt][q] = 0.f;

    const uint2* ub = (const uint2*)g_UaP;
    #pragma unroll
    for (int kt = 0; kt < 8; kt++) {
        uint32_t a[4];
        ldmA(a, &ash[mi * 16 + lrow][kt * 16 + lcol]);
        #pragma unroll
        for (int nt = 0; nt < 4; nt++) {
            int ntg = nw * 4 + nt;
            uint2 b = ub[(ntg * 8 + kt) * 32 + lane];
            mma16816(acc[nt], a, b);
        }
    }
    __syncthreads();

    int g = lane >> 2, tg = lane & 3;
    #pragma unroll
    for (int nt = 0; nt < 4; nt++) {
        int n = (nw * 4 + nt) * 8 + tg * 2;
        *(__half2*)&ash[mi * 16 + g][n]     = __floats2half2_rn(acc[nt][0], acc[nt][1]);
        *(__half2*)&ash[mi * 16 + 8 + g][n] = __floats2half2_rn(acc[nt][2], acc[nt][3]);
    }
    __syncthreads();
    for (int i = tid; i < 512; i += 256) {
        int r = i >> 4, ch = i & 15;
        *(uint4*)&g_Ueh[(row0 + r) * NH + ch * 8] = *(uint4*)&ash[r][ch * 8];
    }
}

// ------------------------- decoder attention (fused single pass, batched loads) ------------
// block: 256 thr = 8 warps; warp = one batch row. Lanes 0-15 even t, 16-31 odd t.
// Per chunk: 8 LDG.128 issued up front (4 pair-iterations) -> high MLP, then 4 indep chains.
// No max subtraction: |score| <= ||va||_1 ~ 9.2, exp() safe in fp32.
__global__ void __launch_bounds__(256) att_kernel(const float* __restrict__ va)
{
    __shared__ float hsh[8][NH];
    __shared__ float qsh[8][NH];
    int tid = threadIdx.x;
    int b0 = blockIdx.x * 8;
    for (int i = tid; i < 8 * NH; i += 256) hsh[i >> 7][i & 127] = g_h[b0 * NH + i];
    __syncthreads();

    // q = h @ Wa^T : thread (u, rh) covers 4 rows
    {
        int u = tid & 127, rh = tid >> 7;
        float qa[4] = {0.f, 0.f, 0.f, 0.f};
        #pragma unroll 4
        for (int k = 0; k < NH; k++) {
            float w = g_WaT[k * NH + u];
            #pragma unroll
            for (int r = 0; r < 4; r++) qa[r] += w * hsh[rh * 4 + r][k];
        }
        #pragma unroll
        for (int r = 0; r < 4; r++) qsh[rh * 4 + r][u] = qa[r];
    }
    __syncthreads();

    int wid = tid >> 5, lane = tid & 31;
    int sub = lane & 15;
    int b = b0 + wid;

    float4 qa = *(float4*)&qsh[wid][sub * 8];
    float4 qb = *(float4*)&qsh[wid][sub * 8 + 4];
    float4 va0 = *(const float4*)&va[sub * 8];
    float4 va1 = *(const float4*)&va[sub * 8 + 4];

    const uint4* uep = (const uint4*)(g_Ueh + (size_t)b * NT * NH) + lane;
    const uint4* ep  = (const uint4*)(g_ench + (size_t)b * NT * NH) + lane;

    float ca[8];
    #pragma unroll
    for (int j = 0; j < 8; j++) ca[j] = 0.f;
    float Z = 0.f;

    // 84 pair-iterations in chunks of 4: all 8 loads first, then 4 independent chains
    #pragma unroll 1
    for (int i0 = 0; i0 < NT / 2; i0 += 4) {
        uint4 UE[4], EN[4];
        #pragma unroll
        for (int j = 0; j < 4; j++) {
            UE[j] = uep[(i0 + j) * 32];
            EN[j] = ep[(i0 + j) * 32];
        }
        float s[4];
        #pragma unroll
        for (int j = 0; j < 4; j++) {
            float2 e0 = __half22float2(*(__half2*)&UE[j].x);
            float2 e1 = __half22float2(*(__half2*)&UE[j].y);
            float2 e2 = __half22float2(*(__half2*)&UE[j].z);
            float2 e3 = __half22float2(*(__half2*)&UE[j].w);
            s[j] = ftanh_fast(e0.x + qa.x) * va0.x + ftanh_fast(e0.y + qa.y) * va0.y
                 + ftanh_fast(e1.x + qa.z) * va0.z + ftanh_fast(e1.y + qa.w) * va0.w
                 + ftanh_fast(e2.x + qb.x) * va1.x + ftanh_fast(e2.y + qb.y) * va1.y
                 + ftanh_fast(e3.x + qb.z) * va1.z + ftanh_fast(e3.y + qb.w) * va1.w;
        }
        // 4 interleaved shfl-trees (independent -> latency overlapped)
        #pragma unroll
        for (int o = 8; o > 0; o >>= 1) {
            #pragma unroll
            for (int j = 0; j < 4; j++)
                s[j] += __shfl_xor_sync(0xffffffffu, s[j], o);
        }
        #pragma unroll
        for (int j = 0; j < 4; j++) {
            float w = __expf(s[j]);
            Z += w;
            float2 n0 = __half22float2(*(__half2*)&EN[j].x);
            float2 n1 = __half22float2(*(__half2*)&EN[j].y);
            float2 n2 = __half22float2(*(__half2*)&EN[j].z);
            float2 n3 = __half22float2(*(__half2*)&EN[j].w);
            ca[0] += w * n0.x; ca[1] += w * n0.y;
            ca[2] += w * n1.x; ca[3] += w * n1.y;
            ca[4] += w * n2.x; ca[5] += w * n2.y;
            ca[6] += w * n3.x; ca[7] += w * n3.y;
        }
    }
    // merge even/odd-t halves (lane j pairs with j+16, same h slice)
    Z += __shfl_xor_sync(0xffffffffu, Z, 16);
    #pragma unroll
    for (int j = 0; j < 8; j++) ca[j] += __shfl_xor_sync(0xffffffffu, ca[j], 16);
    float invZ = __fdividef(1.f, Z);
    if (lane < 16) {
        float4 o0 = {ca[0] * invZ, ca[1] * invZ, ca[2] * invZ, ca[3] * invZ};
        float4 o1 = {ca[4] * invZ, ca[5] * invZ, ca[6] * invZ, ca[7] * invZ};
        *(float4*)&g_ctx[b * NH + sub * 8]     = o0;
        *(float4*)&g_ctx[b * NH + sub * 8 + 4] = o1;
    }
}

// ------------------------- decoder LSTM cell + fc (HMMA, per step) -------------------------
// block: 256 thr = 8 warps, 16 rows (grid 256 > 148 SMs). K=256 over fp16 [ctx|h].
__global__ void __launch_bounds__(256) cell_kernel(const float* __restrict__ x,
                                                   const float* __restrict__ fcW,
                                                   const float* __restrict__ fcb,
                                                   float* __restrict__ out, int step)
{
    __shared__ __half ash[16][264];
    __shared__ float biassh[NG], dinwsh[NG];
    __shared__ float dinsh[16];
    __shared__ float hout[16][NH];
    int tid = threadIdx.x;
    int wid = tid >> 5, lane = tid & 31;
    int b0 = blockIdx.x * 16;
    int g = lane >> 2, tg = lane & 3, tg2 = tg >> 1;
    int odd = tg & 1;
    int lrow = lane & 15;
    int lcol = (lane >> 4) << 3;

    for (int i = tid; i < NG; i += 256) { biassh[i] = g_decBp[i]; dinwsh[i] = g_dinW[i]; }
    for (int i = tid; i < 16 * 64; i += 256) {
        int r = i >> 6, k2 = i & 63;
        float2 cv = ((const float2*)g_ctx)[(size_t)(b0 + r) * 64 + k2];
        float2 hv = ((const float2*)g_h)  [(size_t)(b0 + r) * 64 + k2];
        *(__half2*)&ash[r][k2 * 2]       = __floats2half2_rn(cv.x, cv.y);
        *(__half2*)&ash[r][128 + k2 * 2] = __floats2half2_rn(hv.x, hv.y);
    }
    if (tid < 16) dinsh[tid] = (step == 0) ? x[(b0 + tid) * NT + (NT - 1)] : g_pred[b0 + tid];
    __syncthreads();

    float acc[8][4];
    #pragma unroll
    for (int j = 0; j < 8; j++)
        #pragma unroll
        for (int q = 0; q < 4; q++) acc[j][q] = 0.f;

    const uint2* wbase = ((const uint2*)g_WdP) + wid * 4096 + lane;
    #pragma unroll
    for (int kt = 0; kt < 16; kt++) {
        uint32_t a[4];
        ldmA(a, &ash[lrow][kt * 16 + lcol]);
        #pragma unroll
        for (int j = 0; j < 8; j++) {
            uint2 b = wbase[(kt * 8 + j) * 32];
            mma16816(acc[j], a, b);
        }
    }

    {
        int row = g + (odd ? 8 : 0);
        float dv = dinsh[row];
        #pragma unroll
        for (int j = 0; j < 8; j++) {
            float t0 = __shfl_xor_sync(0xffffffffu, acc[j][0], 1);
            float t1 = __shfl_xor_sync(0xffffffffu, acc[j][1], 1);
            float t2 = __shfl_xor_sync(0xffffffffu, acc[j][2], 1);
            float t3 = __shfl_xor_sync(0xffffffffu, acc[j][3], 1);
            float gi, gf, gg, go;
            if (!odd) { gi = acc[j][0]; gf = acc[j][1]; gg = t0; go = t1; }
            else      { gi = t2; gf = t3; gg = acc[j][2]; go = acc[j][3]; }
            int u = wid * 16 + j * 2 + tg2;
            float4 bi = *(const float4*)&biassh[u * 4];
            float4 wi = *(const float4*)&dinwsh[u * 4];
            gi += bi.x + dv * wi.x;
            gf += bi.y + dv * wi.y;
            gg += bi.z + dv * wi.z;
            go += bi.w + dv * wi.w;
            int b = b0 + row;
            float cold = g_c[b * NH + u];
            float cn = fsig_fast(gf) * cold + fsig_fast(gi) * ftanh_fast(gg);
            float hn = fsig_fast(go) * ftanh_fast(cn);
            g_c[b * NH + u] = cn;
            g_h[b * NH + u] = hn;
            hout[row][u] = hn;
        }
    }
    __syncthreads();

    // pred = h2 @ fcW^T + fcb ; warp handles 2 rows
    float fw0 = fcW[lane], fw1 = fcW[lane + 32], fw2 = fcW[lane + 64], fw3 = fcW[lane + 96];
    #pragma unroll
    for (int rr = 0; rr < 2; rr++) {
        int r = wid * 2 + rr;
        float s = hout[r][lane] * fw0 + hout[r][lane + 32] * fw1
                + hout[r][lane + 64] * fw2 + hout[r][lane + 96] * fw3;
        #pragma unroll
        for (int off = 16; off > 0; off >>= 1) s += __shfl_xor_sync(0xffffffffu, s, off);
        if (lane == 0) {
            float p = s + fcb[0];
            out[(b0 + r) * NO + step] = p;
            g_pred[b0 + r] = p;
        }
    }
}

// ------------------------- launch -------------------------
extern "C" void kernel_launch(void* const* d_in, const int* in_sizes, int n_in,
                              void* d_out, int out_size)
{
    const float* x      = (const float*)d_in[0];
    const float* encWih = (const float*)d_in[1];
    const float* encWhh = (const float*)d_in[2];
    const float* encBih = (const float*)d_in[3];
    const float* encBhh = (const float*)d_in[4];
    const float* Wa     = (const float*)d_in[5];
    const float* Ua     = (const float*)d_in[6];
    const float* va     = (const float*)d_in[7];
    const float* decWih = (const float*)d_in[8];
    const float* decWhh = (const float*)d_in[9];
    const float* decBih = (const float*)d_in[10];
    const float* decBhh = (const float*)d_in[11];
    const float* fcW    = (const float*)d_in[12];
    const float* fcb    = (const float*)d_in[13];
    float* out = (float*)d_out;

    pack_kernel<<<256, 256>>>(encWih, encWhh, encBih, encBhh, Wa, Ua,
                              decWih, decWhh, decBih, decBhh);
    enc_kernel<<<NB / 32, 256>>>(x);
    ue_kernel<<<NB * NT / 32, 256>>>();
    for (int d = 0; d < NO; d++) {
        att_kernel<<<NB / 8, 256>>>(va);
        cell_kernel<<<NB / 16, 256>>>(x, fcW, fcb, out, d);
    }
}

// round 10
// speedup vs baseline: 1.4074x; 1.2608x over previous
#include <cuda_runtime.h>
#include <cuda_fp16.h>
#include <cstdint>

#define NB 4096
#define NT 168
#define NH 128
#define NG 512
#define NO 24

// ------------------------- device scratch -------------------------
__device__ __half g_ench[NB * NT * NH];  // encoder hidden states (B*T, H) fp16
__device__ __half g_Ueh [NB * NT * NH];  // Ua @ enc_outs        (B*T, H) fp16
__device__ float g_h  [NB * NH];
__device__ float g_c  [NB * NH];
__device__ __half g_WencP[8 * 8 * 8 * 32 * 4];  // enc Whh B-frags [wid][kt][j][lane][4]
__device__ __half g_UaP  [16 * 8 * 32 * 4];     // Ua B-frags [nt][kt][lane][4]
__device__ __half g_WdP  [8 * 16 * 8 * 32 * 4]; // dec [Wih(ctx)|Whh] B-frags, K=256
__device__ float g_encBp[NG];           // enc bias, n = u*4+gate
__device__ float g_wihp [NG];           // enc Wih,  n = u*4+gate
__device__ float g_decBp[NG];           // dec bias, n = u*4+gate
__device__ float g_dinW [NG];           // dec Wih col 0 (din), n = u*4+gate
__device__ float g_WaT [NH * NH];       // Wa transposed: [k][u]

// fast activations: tanh.approx (1 MUFU); sigmoid via tanh identity (1 MUFU + 2 FMA)
__device__ __forceinline__ float ftanh_fast(float x) { asm("tanh.approx.f32 %0, %0;" : "+f"(x)); return x; }
__device__ __forceinline__ float fsig_fast(float x)  { return 0.5f + 0.5f * ftanh_fast(0.5f * x); }

// ------------------------- mma helpers -------------------------
__device__ __forceinline__ void ldmA(uint32_t a[4], const __half* p) {
    uint32_t addr = (uint32_t)__cvta_generic_to_shared(p);
    asm volatile("ldmatrix.sync.aligned.m8n8.x4.shared.b16 {%0,%1,%2,%3}, [%4];"
        : "=r"(a[0]), "=r"(a[1]), "=r"(a[2]), "=r"(a[3]) : "r"(addr));
}
__device__ __forceinline__ void mma16816(float c[4], const uint32_t a[4], uint2 b) {
    asm volatile("mma.sync.aligned.m16n8k16.row.col.f32.f16.f16.f32 "
        "{%0,%1,%2,%3},{%4,%5,%6,%7},{%8,%9},{%0,%1,%2,%3};"
        : "+f"(c[0]), "+f"(c[1]), "+f"(c[2]), "+f"(c[3])
        : "r"(a[0]), "r"(a[1]), "r"(a[2]), "r"(a[3]), "r"(b.x), "r"(b.y));
}

// ------------------------- weight packing -------------------------
__global__ void pack_kernel(const float* __restrict__ encWih,
                            const float* __restrict__ encWhh,
                            const float* __restrict__ encBih, const float* __restrict__ encBhh,
                            const float* __restrict__ Wa, const float* __restrict__ Ua,
                            const float* __restrict__ decWih, const float* __restrict__ decWhh,
                            const float* __restrict__ decBih, const float* __restrict__ decBhh)
{
    int stride = gridDim.x * blockDim.x;
    int i0 = blockIdx.x * blockDim.x + threadIdx.x;

    for (int idx = i0; idx < 8 * 8 * 8 * 32 * 4; idx += stride) {
        int q = idx & 3, lane = (idx >> 2) & 31;
        int rest = idx >> 7;
        int j = rest & 7, kt = (rest >> 3) & 7, wid = rest >> 6;
        int g = lane >> 2, tg = lane & 3;
        int n = wid * 64 + j * 8 + g;
        int u = n >> 2, gate = n & 3;
        int k = kt * 16 + ((q < 2) ? (tg * 2 + q) : (tg * 2 + 8 + (q - 2)));
        g_WencP[idx] = __float2half_rn(encWhh[(gate * 128 + u) * NH + k]);
    }
    for (int idx = i0; idx < 8 * 16 * 8 * 32 * 4; idx += stride) {
        int q = idx & 3, lane = (idx >> 2) & 31;
        int rest = idx >> 7;
        int j = rest & 7, kt = (rest >> 3) & 15, wid = rest >> 7;
        int g = lane >> 2, tg = lane & 3;
        int n = wid * 64 + j * 8 + g;
        int u = n >> 2, gate = n & 3;
        int k = kt * 16 + ((q < 2) ? (tg * 2 + q) : (tg * 2 + 8 + (q - 2)));
        float v = (k < NH) ? decWih[(gate * 128 + u) * (NH + 1) + 1 + k]
                           : decWhh[(gate * 128 + u) * NH + (k - NH)];
        g_WdP[idx] = __float2half_rn(v);
    }
    for (int idx = i0; idx < 16 * 8 * 32 * 4; idx += stride) {
        int q = idx & 3, lane = (idx >> 2) & 31;
        int rest = idx >> 7;
        int kt = rest & 7, nt = rest >> 3;
        int g = lane >> 2, tg = lane & 3;
        int n = nt * 8 + g;
        int k = kt * 16 + ((q < 2) ? (tg * 2 + q) : (tg * 2 + 8 + (q - 2)));
        g_UaP[idx] = __float2half_rn(Ua[n * NH + k]);
    }
    for (int i = i0; i < NH * NH; i += stride) {
        int k = i / NH, u = i % NH;
        g_WaT[i] = Wa[u * NH + k];
    }
    for (int i = i0; i < NG; i += stride) {
        int u = i >> 2, gate = i & 3;
        g_encBp[i] = encBih[gate * 128 + u] + encBhh[gate * 128 + u];
        g_wihp[i]  = encWih[gate * 128 + u];
        g_decBp[i] = decBih[gate * 128 + u] + decBhh[gate * 128 + u];
        g_dinW[i]  = decWih[(gate * 128 + u) * (NH + 1)];
    }
}

// ------------------------- encoder (HMMA, one launch, 168 steps) -------------------------
__global__ void __launch_bounds__(256) enc_kernel(const float* __restrict__ x)
{
    __shared__ __half hsh[32][136];
    __shared__ float biassh[NG], wihsh[NG];
    int tid = threadIdx.x;
    int wid = tid >> 5, lane = tid & 31;
    int b0 = blockIdx.x * 32;
    int g = lane >> 2, tg = lane & 3, tg2 = tg >> 1;
    int odd = tg & 1;
    int lrow = lane & 15;
    int lcol = (lane >> 4) << 3;

    for (int i = tid; i < NG; i += 256) { biassh[i] = g_encBp[i]; wihsh[i] = g_wihp[i]; }
    for (int i = tid; i < 32 * 136; i += 256) ((__half*)hsh)[i] = __ushort_as_half(0);

    float cst[16];
    #pragma unroll
    for (int i = 0; i < 16; i++) cst[i] = 0.f;

    const uint2* wbase = ((const uint2*)g_WencP) + wid * 2048 + lane;
    __syncthreads();

    for (int t = 0; t < NT; t++) {
        float xv[2];
        #pragma unroll
        for (int mi = 0; mi < 2; mi++)
            xv[mi] = x[(b0 + mi * 16 + g + (odd ? 8 : 0)) * NT + t];

        float acc[2][8][4];
        #pragma unroll
        for (int mi = 0; mi < 2; mi++)
            #pragma unroll
            for (int j = 0; j < 8; j++)
                #pragma unroll
                for (int q = 0; q < 4; q++) acc[mi][j][q] = 0.f;

        #pragma unroll
        for (int kt = 0; kt < 8; kt++) {
            uint32_t a[2][4];
            #pragma unroll
            for (int mi = 0; mi < 2; mi++)
                ldmA(a[mi], &hsh[mi * 16 + lrow][kt * 16 + lcol]);
            #pragma unroll
            for (int j = 0; j < 8; j++) {
                uint2 b = wbase[(kt * 8 + j) * 32];
                mma16816(acc[0][j], a[0], b);
                mma16816(acc[1][j], a[1], b);
            }
        }
        __syncthreads();

        #pragma unroll
        for (int mi = 0; mi < 2; mi++) {
            int row = mi * 16 + g + (odd ? 8 : 0);
            #pragma unroll
            for (int j = 0; j < 8; j++) {
                float t0 = __shfl_xor_sync(0xffffffffu, acc[mi][j][0], 1);
                float t1 = __shfl_xor_sync(0xffffffffu, acc[mi][j][1], 1);
                float t2 = __shfl_xor_sync(0xffffffffu, acc[mi][j][2], 1);
                float t3 = __shfl_xor_sync(0xffffffffu, acc[mi][j][3], 1);
                float gi, gf, gg, go;
                if (!odd) { gi = acc[mi][j][0]; gf = acc[mi][j][1]; gg = t0; go = t1; }
                else      { gi = t2; gf = t3; gg = acc[mi][j][2]; go = acc[mi][j][3]; }
                int u = wid * 16 + j * 2 + tg2;
                float4 bi = *(const float4*)&biassh[u * 4];
                float4 wi = *(const float4*)&wihsh[u * 4];
                gi += bi.x + xv[mi] * wi.x;
                gf += bi.y + xv[mi] * wi.y;
                gg += bi.z + xv[mi] * wi.z;
                go += bi.w + xv[mi] * wi.w;
                float c = fsig_fast(gf) * cst[mi * 8 + j] + fsig_fast(gi) * ftanh_fast(gg);
                cst[mi * 8 + j] = c;
                float h = fsig_fast(go) * ftanh_fast(c);
                hsh[row][u] = __float2half_rn(h);
            }
        }
        __syncthreads();

        for (int i = tid; i < 512; i += 256) {
            int r = i >> 4, ch = i & 15;
            uint4 v = *(uint4*)&hsh[r][ch * 8];
            *(uint4*)&g_ench[(size_t)(b0 + r) * (NT * NH) + (size_t)t * NH + ch * 8] = v;
        }
    }
    __syncthreads();
    for (int i = tid; i < 32 * NH; i += 256) {
        int r = i >> 7, u2 = i & 127;
        g_h[(b0 + r) * NH + u2] = __half2float(hsh[r][u2]);
    }
    #pragma unroll
    for (int mi = 0; mi < 2; mi++) {
        int row = mi * 16 + g + (odd ? 8 : 0);
        #pragma unroll
        for (int j = 0; j < 8; j++) {
            int u = wid * 16 + j * 2 + tg2;
            g_c[(b0 + row) * NH + u] = cst[mi * 8 + j];
        }
    }
}

// ------------------------- Ue = enc_outs @ Ua^T (HMMA) -------------------------
__global__ void __launch_bounds__(256) ue_kernel()
{
    __shared__ __half ash[32][136];
    int tid = threadIdx.x;
    int wid = tid >> 5, lane = tid & 31;
    size_t row0 = (size_t)blockIdx.x * 32;

    for (int i = tid; i < 512; i += 256) {
        int r = i >> 4, ch = i & 15;
        *(uint4*)&ash[r][ch * 8] = *(const uint4*)&g_ench[(row0 + r) * NH + ch * 8];
    }
    __syncthreads();

    int mi = wid & 1, nw = wid >> 1;
    int lrow = lane & 15, lcol = (lane >> 4) << 3;
    float acc[4][4];
    #pragma unroll
    for (int nt = 0; nt < 4; nt++)
        #pragma unroll
        for (int q = 0; q < 4; q++) acc[nt][q] = 0.f;

    const uint2* ub = (const uint2*)g_UaP;
    #pragma unroll
    for (int kt = 0; kt < 8; kt++) {
        uint32_t a[4];
        ldmA(a, &ash[mi * 16 + lrow][kt * 16 + lcol]);
        #pragma unroll
        for (int nt = 0; nt < 4; nt++) {
            int ntg = nw * 4 + nt;
            uint2 b = ub[(ntg * 8 + kt) * 32 + lane];
            mma16816(acc[nt], a, b);
        }
    }
    __syncthreads();

    int g = lane >> 2, tg = lane & 3;
    #pragma unroll
    for (int nt = 0; nt < 4; nt++) {
        int n = (nw * 4 + nt) * 8 + tg * 2;
        *(__half2*)&ash[mi * 16 + g][n]     = __floats2half2_rn(acc[nt][0], acc[nt][1]);
        *(__half2*)&ash[mi * 16 + 8 + g][n] = __floats2half2_rn(acc[nt][2], acc[nt][3]);
    }
    __syncthreads();
    for (int i = tid; i < 512; i += 256) {
        int r = i >> 4, ch = i & 15;
        *(uint4*)&g_Ueh[(row0 + r) * NH + ch * 8] = *(uint4*)&ash[r][ch * 8];
    }
}

// ------------------------- fused decoder (ONE launch, 24 steps inside) -------------------------
// grid 256 x 512 thr = 16 warps. Block owns 16 batch rows for the whole decoder.
// Per step: q-GEMV (all threads) -> att (warp per row, fused softmax, ctx -> smem fp16)
//          -> cell HMMA (16 warps x 32 gate-cols, K=256 over smem [ctx|h]) -> fc.
// h: f32 in hsh (q-GEMV, fc) + fp16 in ash[.,128..] (mma A). c: registers. pred: smem.
__global__ void __launch_bounds__(512, 2) dec_kernel(const float* __restrict__ x,
                                                     const float* __restrict__ va,
                                                     const float* __restrict__ fcW,
                                                     const float* __restrict__ fcb,
                                                     float* __restrict__ out)
{
    __shared__ __half ash[16][264];     // [row][ ctx fp16 (128) | h fp16 (128) ] (+pad)
    __shared__ float hsh[16][NH];       // h fp32
    __shared__ float qsh[16][NH];       // q = h @ Wa^T
    __shared__ float biassh[NG], dinwsh[NG];
    __shared__ float dinsh[16];
    int tid = threadIdx.x;
    int wid = tid >> 5, lane = tid & 31;
    int b0 = blockIdx.x * 16;
    int g = lane >> 2, tg = lane & 3, tg2 = tg >> 1;
    int odd = tg & 1;
    int lrow = lane & 15;
    int lcol = (lane >> 4) << 3;
    int sub = lane & 15;
    int wq = wid >> 1, jo = (wid & 1) * 4;   // cell: warp covers gate-cols [wq*64 + jo*8, +32)
    int myrow = g + (odd ? 8 : 0);

    for (int i = tid; i < NG; i += 512) { biassh[i] = g_decBp[i]; dinwsh[i] = g_dinW[i]; }
    for (int i = tid; i < 16 * NH; i += 512) {
        int r = i >> 7, k = i & 127;
        float hv = g_h[(b0 + r) * NH + k];
        hsh[r][k] = hv;
        ash[r][128 + k] = __float2half_rn(hv);
    }
    float creg[4];
    #pragma unroll
    for (int j = 0; j < 4; j++) {
        int u = wq * 16 + (jo + j) * 2 + tg2;
        creg[j] = g_c[(b0 + myrow) * NH + u];
    }
    if (tid < 16) dinsh[tid] = x[(b0 + tid) * NT + (NT - 1)];

    // persistent per-thread constants
    float4 va0 = *(const float4*)&va[sub * 8];
    float4 va1 = *(const float4*)&va[sub * 8 + 4];
    float fw0 = fcW[lane], fw1 = fcW[lane + 32], fw2 = fcW[lane + 64], fw3 = fcW[lane + 96];
    float fcbv = fcb[0];
    const uint4* uep = (const uint4*)(g_Ueh + (size_t)(b0 + wid) * NT * NH) + lane;
    const uint4* ep  = (const uint4*)(g_ench + (size_t)(b0 + wid) * NT * NH) + lane;
    const uint2* wbase = ((const uint2*)g_WdP) + wq * 4096 + lane;
    __syncthreads();

    for (int step = 0; step < NO; step++) {
        // ---- q = h @ Wa^T : thread (u, rh) covers 4 rows ----
        {
            int u = tid & 127, rh = tid >> 7;
            float qa[4] = {0.f, 0.f, 0.f, 0.f};
            #pragma unroll 4
            for (int k = 0; k < NH; k++) {
                float w = g_WaT[k * NH + u];
                #pragma unroll
                for (int r = 0; r < 4; r++) qa[r] += w * hsh[rh * 4 + r][k];
            }
            #pragma unroll
            for (int r = 0; r < 4; r++) qsh[rh * 4 + r][u] = qa[r];
        }
        __syncthreads();

        // ---- attention: warp per row, fused single pass ----
        {
            float4 qa = *(float4*)&qsh[wid][sub * 8];
            float4 qb = *(float4*)&qsh[wid][sub * 8 + 4];
            float ca[8];
            #pragma unroll
            for (int j = 0; j < 8; j++) ca[j] = 0.f;
            float Z = 0.f;

            #pragma unroll 2
            for (int i = 0; i < NT / 2; i++) {
                uint4 ue = uep[i * 32];
                uint4 en = ep[i * 32];
                float2 e0 = __half22float2(*(__half2*)&ue.x);
                float2 e1 = __half22float2(*(__half2*)&ue.y);
                float2 e2 = __half22float2(*(__half2*)&ue.z);
                float2 e3 = __half22float2(*(__half2*)&ue.w);
                float s = ftanh_fast(e0.x + qa.x) * va0.x + ftanh_fast(e0.y + qa.y) * va0.y
                        + ftanh_fast(e1.x + qa.z) * va0.z + ftanh_fast(e1.y + qa.w) * va0.w
                        + ftanh_fast(e2.x + qb.x) * va1.x + ftanh_fast(e2.y + qb.y) * va1.y
                        + ftanh_fast(e3.x + qb.z) * va1.z + ftanh_fast(e3.y + qb.w) * va1.w;
                s += __shfl_xor_sync(0xffffffffu, s, 8);
                s += __shfl_xor_sync(0xffffffffu, s, 4);
                s += __shfl_xor_sync(0xffffffffu, s, 2);
                s += __shfl_xor_sync(0xffffffffu, s, 1);
                float w = __expf(s);
                Z += w;
                float2 n0 = __half22float2(*(__half2*)&en.x);
                float2 n1 = __half22float2(*(__half2*)&en.y);
                float2 n2 = __half22float2(*(__half2*)&en.z);
                float2 n3 = __half22float2(*(__half2*)&en.w);
                ca[0] += w * n0.x; ca[1] += w * n0.y;
                ca[2] += w * n1.x; ca[3] += w * n1.y;
                ca[4] += w * n2.x; ca[5] += w * n2.y;
                ca[6] += w * n3.x; ca[7] += w * n3.y;
            }
            Z += __shfl_xor_sync(0xffffffffu, Z, 16);
            #pragma unroll
            for (int j = 0; j < 8; j++) ca[j] += __shfl_xor_sync(0xffffffffu, ca[j], 16);
            float invZ = __fdividef(1.f, Z);
            if (lane < 16) {
                // ctx fp16 straight into mma A-tile
                __half2 h0 = __floats2half2_rn(ca[0] * invZ, ca[1] * invZ);
                __half2 h1 = __floats2half2_rn(ca[2] * invZ, ca[3] * invZ);
                __half2 h2 = __floats2half2_rn(ca[4] * invZ, ca[5] * invZ);
                __half2 h3 = __floats2half2_rn(ca[6] * invZ, ca[7] * invZ);
                uint4 pk;
                pk.x = *(uint32_t*)&h0; pk.y = *(uint32_t*)&h1;
                pk.z = *(uint32_t*)&h2; pk.w = *(uint32_t*)&h3;
                *(uint4*)&ash[wid][sub * 8] = pk;
            }
        }
        __syncthreads();

        // ---- cell HMMA: 16 warps x 4 n8-tiles, K=256 ----
        float acc[4][4];
        #pragma unroll
        for (int j = 0; j < 4; j++)
            #pragma unroll
            for (int q = 0; q < 4; q++) acc[j][q] = 0.f;

        #pragma unroll
        for (int kt = 0; kt < 16; kt++) {
            uint32_t a[4];
            ldmA(a, &ash[lrow][kt * 16 + lcol]);
            #pragma unroll
            for (int j = 0; j < 4; j++) {
                uint2 b = wbase[(kt * 8 + jo + j) * 32];
                mma16816(acc[j], a, b);
            }
        }
        __syncthreads();   // all mma reads of old h done before h update

        {
            float dv = dinsh[myrow];
            #pragma unroll
            for (int j = 0; j < 4; j++) {
                float t0 = __shfl_xor_sync(0xffffffffu, acc[j][0], 1);
                float t1 = __shfl_xor_sync(0xffffffffu, acc[j][1], 1);
                float t2 = __shfl_xor_sync(0xffffffffu, acc[j][2], 1);
                float t3 = __shfl_xor_sync(0xffffffffu, acc[j][3], 1);
                float gi, gf, gg, go;
                if (!odd) { gi = acc[j][0]; gf = acc[j][1]; gg = t0; go = t1; }
                else      { gi = t2; gf = t3; gg = acc[j][2]; go = acc[j][3]; }
                int u = wq * 16 + (jo + j) * 2 + tg2;
                float4 bi = *(const float4*)&biassh[u * 4];
                float4 wi = *(const float4*)&dinwsh[u * 4];
                gi += bi.x + dv * wi.x;
                gf += bi.y + dv * wi.y;
                gg += bi.z + dv * wi.z;
                go += bi.w + dv * wi.w;
                float cn = fsig_fast(gf) * creg[j] + fsig_fast(gi) * ftanh_fast(gg);
                creg[j] = cn;
                float hn = fsig_fast(go) * ftanh_fast(cn);
                hsh[myrow][u] = hn;
                ash[myrow][128 + u] = __float2half_rn(hn);
            }
        }
        __syncthreads();   // h fully updated before fc / next q

        // ---- fc: warp wid -> pred for row wid ----
        {
            float s = hsh[wid][lane] * fw0 + hsh[wid][lane + 32] * fw1
                    + hsh[wid][lane + 64] * fw2 + hsh[wid][lane + 96] * fw3;
            #pragma unroll
            for (int off = 16; off > 0; off >>= 1) s += __shfl_xor_sync(0xffffffffu, s, off);
            if (lane == 0) {
                float p = s + fcbv;
                out[(b0 + wid) * NO + step] = p;
                dinsh[wid] = p;
            }
        }
        __syncthreads();
    }
}

// ------------------------- launch -------------------------
extern "C" void kernel_launch(void* const* d_in, const int* in_sizes, int n_in,
                              void* d_out, int out_size)
{
    const float* x      = (const float*)d_in[0];
    const float* encWih = (const float*)d_in[1];
    const float* encWhh = (const float*)d_in[2];
    const float* encBih = (const float*)d_in[3];
    const float* encBhh = (const float*)d_in[4];
    const float* Wa     = (const float*)d_in[5];
    const float* Ua     = (const float*)d_in[6];
    const float* va     = (const float*)d_in[7];
    const float* decWih = (const float*)d_in[8];
    const float* decWhh = (const float*)d_in[9];
    const float* decBih = (const float*)d_in[10];
    const float* decBhh = (const float*)d_in[11];
    const float* fcW    = (const float*)d_in[12];
    const float* fcb    = (const float*)d_in[13];
    float* out = (float*)d_out;

    pack_kernel<<<256, 256>>>(encWih, encWhh, encBih, encBhh, Wa, Ua,
                              decWih, decWhh, decBih, decBhh);
    enc_kernel<<<NB / 32, 256>>>(x);
    ue_kernel<<<NB * NT / 32, 256>>>();
    dec_kernel<<<NB / 16, 512>>>(x, va, fcW, fcb, out);
}